// round 5
// baseline (speedup 1.0000x reference)
#include <cuda_runtime.h>
#include <cuda_bf16.h>
#include <mma.h>
#include <cstdint>

using namespace nvcuda;

#define KPOLY 3
#define NN 10000
#define SPLITS 12           // 3 polys x 4 K-quarters
#define KSPL 2560           // K per split (last: 2320); 64-aligned boundaries
#define KCH 32
#define MTILE 128
#define MT ((NN + MTILE - 1) / MTILE)  // 79

// ---------------- scratch (static device arrays; no allocation) ----------------
__device__ __align__(16) unsigned short g_T1h[(size_t)64 * KPOLY * NN];
__device__ __align__(16) unsigned short g_T1l[(size_t)64 * KPOLY * NN];
__device__ __align__(16) unsigned short g_T2h[(size_t)32 * KPOLY * NN];
__device__ __align__(16) unsigned short g_T2l[(size_t)32 * KPOLY * NN];
__device__ __align__(16) unsigned short g_Ah[(size_t)KPOLY * NN * NN];  // presplit poly hi
__device__ __align__(16) unsigned short g_Al[(size_t)KPOLY * NN * NN];  // presplit poly lo
__device__ float g_P1[(size_t)SPLITS * NN * 64];
__device__ float g_P2[(size_t)SPLITS * NN * 32];

__device__ __forceinline__ uint32_t smem_u32(const void* p) {
    uint32_t a;
    asm("{ .reg .u64 t; cvta.to.shared.u64 t, %1; cvt.u32.u64 %0, t; }" : "=r"(a) : "l"(p));
    return a;
}

// exact two-term split: x = hi + lo (hi = RNE bf16 of x); hi2 packs two hi's
__device__ __forceinline__ void split2(float x, float y, uint32_t& hi2, float& lx, float& ly) {
    uint32_t ux = __float_as_uint(x);
    uint32_t rx = (ux + 0x7FFFu + ((ux >> 16) & 1u)) & 0xFFFF0000u;
    uint32_t uy = __float_as_uint(y);
    uint32_t ry = (uy + 0x7FFFu + ((uy >> 16) & 1u)) & 0xFFFF0000u;
    hi2 = (rx >> 16) | (ry & 0xFFFF0000u);
    lx = x - __uint_as_float(rx);
    ly = y - __uint_as_float(ry);
}
__device__ __forceinline__ uint32_t pkbf(float a, float b) {  // a -> low 16 bits
    uint32_t r;
    asm("cvt.rn.bf16x2.f32 %0, %1, %2;" : "=r"(r) : "f"(b), "f"(a));
    return r;
}

#define CP_ASYNC(dst, src, pb) \
    asm volatile("cp.async.cg.shared.global [%0], [%1], 16, %2;" \
        :: "r"(dst), "l"(src), "r"(pb) : "memory")
#define CP_COMMIT() asm volatile("cp.async.commit_group;" ::: "memory")
#define CP_WAIT1()  asm volatile("cp.async.wait_group 1;" ::: "memory")

// =======================================================================
// Layer-1 fused kernel (C=64): warp-specialized.
//   warps 0-7  (256 thr): B cp.async + LDSM + HMMA (3-pass split bf16)
//   warps 8-11 (128 thr): poly fp32 LDG -> exact split -> STS + presplit STG
// 3-stage smem pipeline, one __syncthreads per chunk.
// =======================================================================
__global__ void __launch_bounds__(384, 2)
poly1_fused_kernel(const float* __restrict__ poly,
                   const unsigned short* __restrict__ Bhg,
                   const unsigned short* __restrict__ Blg,
                   unsigned short* __restrict__ Ahg,
                   unsigned short* __restrict__ Alg,
                   float* __restrict__ P) {
    constexpr int C = 64;
    constexpr int LDA = 32, LDB = 40;
    constexpr int ABYT = MTILE * LDA * 2;  // 8192 per plane per stage
    constexpr int BBYT = C * LDB * 2;      // 5120
    constexpr int SS = 2 * ABYT + 2 * BBYT;  // 26624
    constexpr int NT = C / 16;
    extern __shared__ __align__(128) char smem[];
    const uint32_t sb = smem_u32(smem);

    const int tid = threadIdx.x;
    const int warp = tid >> 5;
    const bool producer = (warp >= 8);
    const int split = blockIdx.y;
    const int k = split >> 2;
    const int mbase = (split & 3) * KSPL;
    const int klen = min(NN - mbase, KSPL);
    const int nch = (klen + KCH - 1) / KCH;
    const int row0 = blockIdx.x * MTILE;

    // ---------------- producer state ----------------
    const int prow = tid - 256;  // 0..127 (valid when producer)
    const int parow = min(row0 + (prow & 127), NN - 1);
    const float* abase = poly + (size_t)k * NN * NN + (size_t)parow * NN + mbase;
    unsigned short* agH = Ahg + ((size_t)k * NN + parow) * NN + mbase;
    unsigned short* agL = Alg + ((size_t)k * NN + parow) * NN + mbase;

    float4 a[8];
    auto loadA = [&](int ch) {  // whole 32-col row of next chunk into regs
        const int mc = ch * KCH;
        const int kv = klen - mc;
#pragma unroll
        for (int j = 0; j < 8; j++) {
            const int cc = j * 4;
            if (cc < kv) a[j] = *(const float4*)(abase + mc + cc);
            else a[j] = make_float4(0.f, 0.f, 0.f, 0.f);
        }
    };
    auto storeA = [&](int ch) {  // split -> STS stage(ch%3) + STG planes
        const int mc = ch * KCH;
        const int kv = klen - mc;
        char* Ah = smem + (ch % 3) * SS;
        char* Al = Ah + ABYT;
        uint32_t h[16], lp[16];
#pragma unroll
        for (int j = 0; j < 8; j++) {
            float l0, l1, l2, l3;
            split2(a[j].x, a[j].y, h[2 * j], l0, l1);
            split2(a[j].z, a[j].w, h[2 * j + 1], l2, l3);
            lp[2 * j] = pkbf(l0, l1);
            lp[2 * j + 1] = pkbf(l2, l3);
            *(uint2*)(Ah + (prow * LDA + j * 4) * 2) = make_uint2(h[2 * j], h[2 * j + 1]);
            *(uint2*)(Al + (prow * LDA + j * 4) * 2) = make_uint2(lp[2 * j], lp[2 * j + 1]);
        }
#pragma unroll
        for (int g = 0; g < 4; g++) {
            const int cc = g * 8;
            if (cc < kv) {  // kv multiple of 16 => 8-col group fully valid
                *(uint4*)(agH + mc + cc) = make_uint4(h[4 * g], h[4 * g + 1], h[4 * g + 2], h[4 * g + 3]);
                *(uint4*)(agL + mc + cc) = make_uint4(lp[4 * g], lp[4 * g + 1], lp[4 * g + 2], lp[4 * g + 3]);
            }
        }
    };

    // ---------------- consumer state ----------------
    const int bc = tid >> 2, bk8 = (tid & 3) * 8;  // tid<256: bc 0..63
    const unsigned short* bsrcH = Bhg + ((size_t)bc * KPOLY + k) * NN + mbase + bk8;
    const unsigned short* bsrcL = Blg + ((size_t)bc * KPOLY + k) * NN + mbase + bk8;
    const uint32_t bdoff = (uint32_t)((bc * LDB + bk8) * 2);
    auto issueB = [&](int ch) {
        const int mc = ch * KCH;
        const int kv = klen - mc;
        const int pb = (bk8 < kv) ? 16 : 0;
        const unsigned short* sh = pb ? (bsrcH + mc) : bsrcH;
        const unsigned short* sl = pb ? (bsrcL + mc) : bsrcL;
        const uint32_t d = sb + ((ch % 3) * SS + 2 * ABYT) + bdoff;
        CP_ASYNC(d, sh, pb);
        CP_ASYNC(d + BBYT, sl, pb);
    };

    wmma::fragment<wmma::accumulator, 16, 16, 16, float> acc[NT];
#pragma unroll
    for (int n = 0; n < NT; n++) wmma::fill_fragment(acc[n], 0.0f);

    auto domma = [&](int ch) {
        const __nv_bfloat16* Ahp = (const __nv_bfloat16*)(smem + (ch % 3) * SS);
        const __nv_bfloat16* Alp = Ahp + MTILE * LDA;
        const __nv_bfloat16* Bhp = (const __nv_bfloat16*)(smem + (ch % 3) * SS + 2 * ABYT);
        const __nv_bfloat16* Blp = Bhp + C * LDB;
#pragma unroll
        for (int ks = 0; ks < 2; ks++) {
            wmma::fragment<wmma::matrix_a, 16, 16, 16, __nv_bfloat16, wmma::row_major> fah, fal;
            wmma::load_matrix_sync(fah, Ahp + warp * 16 * LDA + ks * 16, LDA);
            wmma::load_matrix_sync(fal, Alp + warp * 16 * LDA + ks * 16, LDA);
#pragma unroll
            for (int n = 0; n < NT; n++) {
                wmma::fragment<wmma::matrix_b, 16, 16, 16, __nv_bfloat16, wmma::col_major> fbh, fbl;
                wmma::load_matrix_sync(fbh, Bhp + n * 16 * LDB + ks * 16, LDB);
                wmma::load_matrix_sync(fbl, Blp + n * 16 * LDB + ks * 16, LDB);
                wmma::mma_sync(acc[n], fah, fbh, acc[n]);
                wmma::mma_sync(acc[n], fah, fbl, acc[n]);
                wmma::mma_sync(acc[n], fal, fbh, acc[n]);
            }
        }
    };

    // ---------------- prologue ----------------
    if (producer) {
        loadA(0);
        storeA(0);
        loadA(1);
    } else {
        issueB(0); CP_COMMIT();
        issueB(1); CP_COMMIT();
    }

    // ---------------- mainloop ----------------
    // iter ch: producer stores stage ch+1 (== stage of MMA(ch-2), retired),
    //          prefetches ch+2; consumer waits group(ch); barrier; consumer
    //          issues B(ch+2) and computes MMA(ch).
    for (int ch = 0; ch < nch; ch++) {
        if (producer) {
            storeA(ch + 1);
            loadA(ch + 2);
        } else {
            CP_WAIT1();
        }
        __syncthreads();
        if (!producer) {
            issueB(ch + 2); CP_COMMIT();
            domma(ch);
        }
    }

    // ---------------- epilogue ----------------
    const int nrow = row0 + warp * 16;
    if (!producer && nrow < NN) {
        float* o = P + ((size_t)split * NN + nrow) * C;
#pragma unroll
        for (int n = 0; n < NT; n++)
            wmma::store_matrix_sync(o + n * 16, acc[n], C, wmma::mem_row_major);
    }
}

// =======================================================================
// Layer-2 kernel (C=32): pure PRE path (proven in round 4).
// =======================================================================
__global__ void __launch_bounds__(256, 3)
poly2_mma_kernel(const unsigned short* __restrict__ Bhg,
                 const unsigned short* __restrict__ Blg,
                 const unsigned short* __restrict__ Ahg,
                 const unsigned short* __restrict__ Alg,
                 float* __restrict__ P) {
    constexpr int C = 32;
    constexpr int LDA = 32, LDB = 40;
    constexpr int ABYT = MTILE * LDA * 2;
    constexpr int BBYT = C * LDB * 2;
    constexpr int SS = 2 * ABYT + 2 * BBYT;
    constexpr int NT = C / 16;
    extern __shared__ __align__(128) char smem[];
    const uint32_t sb = smem_u32(smem);

    const int tid = threadIdx.x;
    const int warp = tid >> 5;
    const int split = blockIdx.y;
    const int k = split >> 2;
    const int mbase = (split & 3) * KSPL;
    const int klen = min(NN - mbase, KSPL);
    const int nch = (klen + KCH - 1) / KCH;
    const int row0 = blockIdx.x * MTILE;

    const int bc = tid >> 2, bk8 = (tid & 3) * 8;
    const unsigned short* bsrcH = Bhg + ((size_t)bc * KPOLY + k) * NN + mbase + bk8;
    const unsigned short* bsrcL = Blg + ((size_t)bc * KPOLY + k) * NN + mbase + bk8;
    const uint32_t bdoff = (uint32_t)((bc * LDB + bk8) * 2);
    auto issueB = [&](int ch) {
        if (tid < 128) {
            const int mc = ch * KCH;
            const int kv = klen - mc;
            const int pb = (bk8 < kv) ? 16 : 0;
            const unsigned short* sh = pb ? (bsrcH + mc) : bsrcH;
            const unsigned short* sl = pb ? (bsrcL + mc) : bsrcL;
            const uint32_t d = sb + ((ch % 3) * SS + 2 * ABYT) + bdoff;
            CP_ASYNC(d, sh, pb);
            CP_ASYNC(d + BBYT, sl, pb);
        }
    };

    const int ar2 = tid >> 2, ak8 = (tid & 3) * 8;
    const unsigned short* asrcH[2];
    const unsigned short* asrcL[2];
    uint32_t adoff[2];
#pragma unroll
    for (int q = 0; q < 2; q++) {
        const int r = ar2 + q * 64;
        const int arow = min(row0 + r, NN - 1);
        asrcH[q] = Ahg + ((size_t)k * NN + arow) * NN + mbase + ak8;
        asrcL[q] = Alg + ((size_t)k * NN + arow) * NN + mbase + ak8;
        adoff[q] = (uint32_t)((r * LDA + ak8) * 2);
    }
    auto issueA = [&](int ch) {
        const int mc = ch * KCH;
        const int kv = klen - mc;
        const int pb = (ak8 < kv) ? 16 : 0;
        const uint32_t base = sb + (ch % 3) * SS;
#pragma unroll
        for (int q = 0; q < 2; q++) {
            const unsigned short* sh = pb ? (asrcH[q] + mc) : asrcH[q];
            const unsigned short* sl = pb ? (asrcL[q] + mc) : asrcL[q];
            CP_ASYNC(base + adoff[q], sh, pb);
            CP_ASYNC(base + ABYT + adoff[q], sl, pb);
        }
    };

    wmma::fragment<wmma::accumulator, 16, 16, 16, float> acc[NT];
#pragma unroll
    for (int n = 0; n < NT; n++) wmma::fill_fragment(acc[n], 0.0f);

    auto domma = [&](int ch) {
        const __nv_bfloat16* Ahp = (const __nv_bfloat16*)(smem + (ch % 3) * SS);
        const __nv_bfloat16* Alp = Ahp + MTILE * LDA;
        const __nv_bfloat16* Bhp = (const __nv_bfloat16*)(smem + (ch % 3) * SS + 2 * ABYT);
        const __nv_bfloat16* Blp = Bhp + C * LDB;
#pragma unroll
        for (int ks = 0; ks < 2; ks++) {
            wmma::fragment<wmma::matrix_a, 16, 16, 16, __nv_bfloat16, wmma::row_major> fah, fal;
            wmma::load_matrix_sync(fah, Ahp + warp * 16 * LDA + ks * 16, LDA);
            wmma::load_matrix_sync(fal, Alp + warp * 16 * LDA + ks * 16, LDA);
            wmma::fragment<wmma::matrix_b, 16, 16, 16, __nv_bfloat16, wmma::col_major> fbh[NT];
#pragma unroll
            for (int n = 0; n < NT; n++)
                wmma::load_matrix_sync(fbh[n], Bhp + n * 16 * LDB + ks * 16, LDB);
#pragma unroll
            for (int n = 0; n < NT; n++) wmma::mma_sync(acc[n], fah, fbh[n], acc[n]);
            {
                wmma::fragment<wmma::matrix_b, 16, 16, 16, __nv_bfloat16, wmma::col_major> fbl;
#pragma unroll
                for (int n = 0; n < NT; n++) {
                    wmma::load_matrix_sync(fbl, Blp + n * 16 * LDB + ks * 16, LDB);
                    wmma::mma_sync(acc[n], fah, fbl, acc[n]);
                }
            }
#pragma unroll
            for (int n = 0; n < NT; n++) wmma::mma_sync(acc[n], fal, fbh[n], acc[n]);
        }
    };

    issueB(0); issueA(0); CP_COMMIT();
    issueB(1); issueA(1); CP_COMMIT();

    for (int ch = 0; ch < nch; ch++) {
        CP_WAIT1();
        __syncthreads();
        issueB(ch + 2); issueA(ch + 2); CP_COMMIT();
        domma(ch);
    }

    const int nrow = row0 + warp * 16;
    if (nrow < NN) {
        float* o = P + ((size_t)split * NN + nrow) * C;
#pragma unroll
        for (int n = 0; n < NT; n++)
            wmma::store_matrix_sync(o + n * 16, acc[n], C, wmma::mem_row_major);
    }
}

// =======================================================================
// Small GEMM: Tt[c][k][n] = (X @ W[k])[n][c] split into bf16 hi/lo.
// RED: X := relu(sum_s P1[s]) read on the fly.
// =======================================================================
template <int DOUT, bool RED>
__global__ void __launch_bounds__(256)
gemm_xw_kernel(const float* __restrict__ X, const float* __restrict__ W,
               unsigned short* __restrict__ Th, unsigned short* __restrict__ Tl) {
    constexpr int DIN = 64;
    constexpr int MR = 256 / (DOUT / 8);
    __shared__ float Ws[DIN * DOUT];
    __shared__ float Xs[MR * (DIN + 1)];
    const int tid = threadIdx.x;
    const int kb = blockIdx.y;
    const int m0 = blockIdx.x * MR;

    for (int i = tid; i < DIN * DOUT; i += 256)
        Ws[i] = W[(size_t)kb * DIN * DOUT + i];
    for (int i = tid; i < MR * DIN; i += 256) {
        int r = i >> 6, d = i & 63;
        int n = m0 + r;
        if (n > NN - 1) n = NN - 1;
        float v;
        if (!RED) {
            v = X[(size_t)n * DIN + d];
        } else {
            v = 0.f;
#pragma unroll
            for (int s = 0; s < SPLITS; s++) v += g_P1[((size_t)s * NN + n) * 64 + d];
            v = fmaxf(v, 0.f);
        }
        Xs[r * (DIN + 1) + d] = v;
    }
    __syncthreads();

    const int row = tid % MR;
    const int c0 = (tid / MR) * 8;
    float a[8];
#pragma unroll
    for (int c = 0; c < 8; c++) a[c] = 0.f;
#pragma unroll
    for (int d = 0; d < DIN; d++) {
        float xv = Xs[row * (DIN + 1) + d];
        float4 wa = *(const float4*)&Ws[d * DOUT + c0];
        float4 wb = *(const float4*)&Ws[d * DOUT + c0 + 4];
        a[0] = fmaf(xv, wa.x, a[0]); a[1] = fmaf(xv, wa.y, a[1]);
        a[2] = fmaf(xv, wa.z, a[2]); a[3] = fmaf(xv, wa.w, a[3]);
        a[4] = fmaf(xv, wb.x, a[4]); a[5] = fmaf(xv, wb.y, a[5]);
        a[6] = fmaf(xv, wb.z, a[6]); a[7] = fmaf(xv, wb.w, a[7]);
    }
    const int n = m0 + row;
    if (n < NN) {
#pragma unroll
        for (int c = 0; c < 8; c++) {
            float v = a[c];
            uint32_t u = __float_as_uint(v);
            uint32_t r = (u + 0x7FFFu + ((u >> 16) & 1u)) & 0xFFFF0000u;
            float lof = v - __uint_as_float(r);
            unsigned short ls;
            asm("cvt.rn.bf16.f32 %0, %1;" : "=h"(ls) : "f"(lof));
            size_t idx = ((size_t)(c0 + c) * KPOLY + kb) * NN + n;
            Th[idx] = (unsigned short)(r >> 16);
            Tl[idx] = ls;
        }
    }
}

// Final reduction of layer-1 partials into d_out
__global__ void reduce_out_kernel(float* __restrict__ out) {
    int i = blockIdx.x * blockDim.x + threadIdx.x;
    if (i < NN * 32 / 4) {
        float4 acc = make_float4(0.f, 0.f, 0.f, 0.f);
#pragma unroll
        for (int s = 0; s < SPLITS; s++) {
            float4 v = *(const float4*)(g_P2 + (size_t)s * NN * 32 + (size_t)i * 4);
            acc.x += v.x; acc.y += v.y; acc.z += v.z; acc.w += v.w;
        }
        *(float4*)(out + (size_t)i * 4) = acc;
    }
}

extern "C" void kernel_launch(void* const* d_in, const int* in_sizes, int n_in,
                              void* d_out, int out_size) {
    const float* x    = (const float*)d_in[0];
    const float* poly = (const float*)d_in[1];
    const float* W1   = (const float*)d_in[2];
    const float* W2   = (const float*)d_in[3];
    float* out = (float*)d_out;

    constexpr int SMEM1 = 3 * (2 * (MTILE * 32 * 2) + 2 * (64 * 40 * 2));  // 79872
    constexpr int SMEM2 = 3 * (2 * (MTILE * 32 * 2) + 2 * (32 * 40 * 2));  // 64512
    cudaFuncSetAttribute((const void*)poly1_fused_kernel,
                         cudaFuncAttributeMaxDynamicSharedMemorySize, SMEM1);
    cudaFuncSetAttribute((const void*)poly2_mma_kernel,
                         cudaFuncAttributeMaxDynamicSharedMemorySize, SMEM2);

    unsigned short *T1h, *T1l, *T2h, *T2l, *Ah, *Al;
    float *P1, *P2;
    cudaGetSymbolAddress((void**)&T1h, g_T1h);
    cudaGetSymbolAddress((void**)&T1l, g_T1l);
    cudaGetSymbolAddress((void**)&T2h, g_T2h);
    cudaGetSymbolAddress((void**)&T2l, g_T2l);
    cudaGetSymbolAddress((void**)&Ah, g_Ah);
    cudaGetSymbolAddress((void**)&Al, g_Al);
    cudaGetSymbolAddress((void**)&P1, g_P1);
    cudaGetSymbolAddress((void**)&P2, g_P2);

    dim3 g1((NN + 31) / 32, KPOLY);
    dim3 g2((NN + 63) / 64, KPOLY);
    dim3 gp(MT, SPLITS);

    gemm_xw_kernel<64, false><<<g1, 256>>>(x, W1, T1h, T1l);
    poly1_fused_kernel<<<gp, 384, SMEM1>>>(poly, T1h, T1l, Ah, Al, P1);
    gemm_xw_kernel<32, true><<<g2, 256>>>(x, W2, T2h, T2l);
    poly2_mma_kernel<<<gp, 256, SMEM2>>>(T2h, T2l, Ah, Al, P2);
    reduce_out_kernel<<<(NN * 32 / 4 + 255) / 256, 256>>>(out);
}

// round 6
// speedup vs baseline: 1.4136x; 1.4136x over previous
#include <cuda_runtime.h>
#include <cuda_bf16.h>
#include <mma.h>
#include <cstdint>

using namespace nvcuda;

#define KPOLY 3
#define NN 10000
#define SPLITS 12           // 3 polys x 4 K-quarters
#define KSPL 2560           // K per split (last: 2320); 64-aligned boundaries
#define KCH 32
#define MTILE 128
#define MT ((NN + MTILE - 1) / MTILE)  // 79
#define TOTE ((size_t)KPOLY * NN * NN) // 3e8 poly elements

// ---------------- scratch (static device arrays; no allocation) ----------------
__device__ __align__(16) unsigned short g_T1h[(size_t)64 * KPOLY * NN];
__device__ __align__(16) unsigned short g_T1l[(size_t)64 * KPOLY * NN];
__device__ __align__(16) unsigned short g_T2h[(size_t)32 * KPOLY * NN];
__device__ __align__(16) unsigned short g_T2l[(size_t)32 * KPOLY * NN];
__device__ __align__(16) unsigned short g_Ah[TOTE];  // presplit poly hi (trunc16)
__device__ __align__(16) unsigned short g_Al[TOTE];  // presplit poly lo
__device__ float g_P1[(size_t)SPLITS * NN * 64];
__device__ float g_P2[(size_t)SPLITS * NN * 32];

__device__ __forceinline__ uint32_t smem_u32(const void* p) {
    uint32_t a;
    asm("{ .reg .u64 t; cvta.to.shared.u64 t, %1; cvt.u32.u64 %0, t; }" : "=r"(a) : "l"(p));
    return a;
}
__device__ __forceinline__ uint32_t prmt7632(uint32_t a, uint32_t b) {
    uint32_t r;
    asm("prmt.b32 %0, %1, %2, 0x7632;" : "=r"(r) : "r"(a), "r"(b));
    return r;
}
__device__ __forceinline__ uint32_t pkbf(float a, float b) {  // a -> low 16 bits (RNE)
    uint32_t r;
    asm("cvt.rn.bf16x2.f32 %0, %1, %2;" : "=r"(r) : "f"(b), "f"(a));
    return r;
}

#define CP_ASYNC(dst, src, pb) \
    asm volatile("cp.async.cg.shared.global [%0], [%1], 16, %2;" \
        :: "r"(dst), "l"(src), "r"(pb) : "memory")
#define CP_COMMIT() asm volatile("cp.async.commit_group;" ::: "memory")
#define CP_WAIT1()  asm volatile("cp.async.wait_group 1;" ::: "memory")

// =======================================================================
// presplit kernel: poly fp32 -> (hi, lo) bf16 planes. Pure streaming.
// hi = trunc16(x) (exact prefix), lo = RNE-bf16(x - hi) (exact two-term
// up to lo's own 2^-16-relative rounding). 16 elems per thread.
// =======================================================================
__global__ void __launch_bounds__(256)
presplit_kernel(const float* __restrict__ poly,
                unsigned short* __restrict__ Ah,
                unsigned short* __restrict__ Al) {
    const size_t base = ((size_t)blockIdx.x * 256 + threadIdx.x) * 16;
    if (base >= TOTE) return;
    const float4* src = (const float4*)(poly + base);
    uint32_t h[8], l[8];
#pragma unroll
    for (int j = 0; j < 4; j++) {
        float4 v = src[j];
        uint32_t ux = __float_as_uint(v.x), uy = __float_as_uint(v.y);
        uint32_t uz = __float_as_uint(v.z), uw = __float_as_uint(v.w);
        h[2 * j]     = prmt7632(ux, uy);
        h[2 * j + 1] = prmt7632(uz, uw);
        float lx = v.x - __uint_as_float(ux & 0xFFFF0000u);
        float ly = v.y - __uint_as_float(uy & 0xFFFF0000u);
        float lz = v.z - __uint_as_float(uz & 0xFFFF0000u);
        float lw = v.w - __uint_as_float(uw & 0xFFFF0000u);
        l[2 * j]     = pkbf(lx, ly);
        l[2 * j + 1] = pkbf(lz, lw);
    }
    uint4* dh = (uint4*)(Ah + base);
    uint4* dl = (uint4*)(Al + base);
    dh[0] = make_uint4(h[0], h[1], h[2], h[3]);
    dh[1] = make_uint4(h[4], h[5], h[6], h[7]);
    dl[0] = make_uint4(l[0], l[1], l[2], l[3]);
    dl[1] = make_uint4(l[4], l[5], l[6], l[7]);
}

// =======================================================================
// poly MMA kernel (PRE): P[split] = poly_slice @ T_slice, all operands
// pre-split bf16 planes via cp.async. 3-stage pipeline, KCH=32,
// pass-major MMA. Proven structure (round-4 PRE, 316us at C=32).
// =======================================================================
template <int C>
__global__ void __launch_bounds__(256, (C == 32) ? 3 : 2)
poly_mma_kernel(const unsigned short* __restrict__ Bhg,
                const unsigned short* __restrict__ Blg,
                const unsigned short* __restrict__ Ahg,
                const unsigned short* __restrict__ Alg,
                float* __restrict__ P) {
    constexpr int LDA = 32, LDB = 40;
    constexpr int ABYT = MTILE * LDA * 2;
    constexpr int BBYT = C * LDB * 2;
    constexpr int SS = 2 * ABYT + 2 * BBYT;
    constexpr int NT = C / 16;
    extern __shared__ __align__(128) char smem[];
    const uint32_t sb = smem_u32(smem);

    const int tid = threadIdx.x;
    const int warp = tid >> 5;
    const int split = blockIdx.y;
    const int k = split >> 2;
    const int mbase = (split & 3) * KSPL;
    const int klen = min(NN - mbase, KSPL);
    const int nch = (klen + KCH - 1) / KCH;
    const int row0 = blockIdx.x * MTILE;

    const int bc = tid >> 2, bk8 = (tid & 3) * 8;
    const unsigned short* bsrcH = Bhg + ((size_t)bc * KPOLY + k) * NN + mbase + bk8;
    const unsigned short* bsrcL = Blg + ((size_t)bc * KPOLY + k) * NN + mbase + bk8;
    const uint32_t bdoff = (uint32_t)((bc * LDB + bk8) * 2);
    auto issueB = [&](int ch) {
        if (C == 64 || tid < 128) {
            const int mc = ch * KCH;
            const int kv = klen - mc;
            const int pb = (bk8 < kv) ? 16 : 0;
            const unsigned short* sh = pb ? (bsrcH + mc) : bsrcH;
            const unsigned short* sl = pb ? (bsrcL + mc) : bsrcL;
            const uint32_t d = sb + ((ch % 3) * SS + 2 * ABYT) + bdoff;
            CP_ASYNC(d, sh, pb);
            CP_ASYNC(d + BBYT, sl, pb);
        }
    };

    const int ar2 = tid >> 2, ak8 = (tid & 3) * 8;
    const unsigned short* asrcH[2];
    const unsigned short* asrcL[2];
    uint32_t adoff[2];
#pragma unroll
    for (int q = 0; q < 2; q++) {
        const int r = ar2 + q * 64;
        const int arow = min(row0 + r, NN - 1);  // clamp; those rows discarded at store
        asrcH[q] = Ahg + ((size_t)k * NN + arow) * NN + mbase + ak8;
        asrcL[q] = Alg + ((size_t)k * NN + arow) * NN + mbase + ak8;
        adoff[q] = (uint32_t)((r * LDA + ak8) * 2);
    }
    auto issueA = [&](int ch) {
        const int mc = ch * KCH;
        const int kv = klen - mc;
        const int pb = (ak8 < kv) ? 16 : 0;
        const uint32_t base = sb + (ch % 3) * SS;
#pragma unroll
        for (int q = 0; q < 2; q++) {
            const unsigned short* sh = pb ? (asrcH[q] + mc) : asrcH[q];
            const unsigned short* sl = pb ? (asrcL[q] + mc) : asrcL[q];
            CP_ASYNC(base + adoff[q], sh, pb);
            CP_ASYNC(base + ABYT + adoff[q], sl, pb);
        }
    };

    wmma::fragment<wmma::accumulator, 16, 16, 16, float> acc[NT];
#pragma unroll
    for (int n = 0; n < NT; n++) wmma::fill_fragment(acc[n], 0.0f);

    auto domma = [&](int ch) {
        const __nv_bfloat16* Ahp = (const __nv_bfloat16*)(smem + (ch % 3) * SS);
        const __nv_bfloat16* Alp = Ahp + MTILE * LDA;
        const __nv_bfloat16* Bhp = (const __nv_bfloat16*)(smem + (ch % 3) * SS + 2 * ABYT);
        const __nv_bfloat16* Blp = Bhp + C * LDB;
#pragma unroll
        for (int ks = 0; ks < 2; ks++) {
            wmma::fragment<wmma::matrix_a, 16, 16, 16, __nv_bfloat16, wmma::row_major> fah, fal;
            wmma::load_matrix_sync(fah, Ahp + warp * 16 * LDA + ks * 16, LDA);
            wmma::load_matrix_sync(fal, Alp + warp * 16 * LDA + ks * 16, LDA);
            wmma::fragment<wmma::matrix_b, 16, 16, 16, __nv_bfloat16, wmma::col_major> fbh[NT];
#pragma unroll
            for (int n = 0; n < NT; n++)
                wmma::load_matrix_sync(fbh[n], Bhp + n * 16 * LDB + ks * 16, LDB);
#pragma unroll
            for (int n = 0; n < NT; n++) wmma::mma_sync(acc[n], fah, fbh[n], acc[n]);
            {
                wmma::fragment<wmma::matrix_b, 16, 16, 16, __nv_bfloat16, wmma::col_major> fbl;
#pragma unroll
                for (int n = 0; n < NT; n++) {
                    wmma::load_matrix_sync(fbl, Blp + n * 16 * LDB + ks * 16, LDB);
                    wmma::mma_sync(acc[n], fah, fbl, acc[n]);
                }
            }
#pragma unroll
            for (int n = 0; n < NT; n++) wmma::mma_sync(acc[n], fal, fbh[n], acc[n]);
        }
    };

    issueB(0); issueA(0); CP_COMMIT();
    issueB(1); issueA(1); CP_COMMIT();

    for (int ch = 0; ch < nch; ch++) {
        CP_WAIT1();
        __syncthreads();
        issueB(ch + 2); issueA(ch + 2); CP_COMMIT();
        domma(ch);
    }

    const int nrow = row0 + warp * 16;  // warp tile fully valid or invalid (10000-9984=16)
    if (nrow < NN) {
        float* o = P + ((size_t)split * NN + nrow) * C;
#pragma unroll
        for (int n = 0; n < NT; n++)
            wmma::store_matrix_sync(o + n * 16, acc[n], C, wmma::mem_row_major);
    }
}

// =======================================================================
// Small GEMM: Tt[c][k][n] = (X @ W[k])[n][c] split into bf16 hi/lo (RNE).
// RED: X := relu(sum_s P1[s]) read on the fly.
// =======================================================================
template <int DOUT, bool RED>
__global__ void __launch_bounds__(256)
gemm_xw_kernel(const float* __restrict__ X, const float* __restrict__ W,
               unsigned short* __restrict__ Th, unsigned short* __restrict__ Tl) {
    constexpr int DIN = 64;
    constexpr int MR = 256 / (DOUT / 8);
    __shared__ float Ws[DIN * DOUT];
    __shared__ float Xs[MR * (DIN + 1)];
    const int tid = threadIdx.x;
    const int kb = blockIdx.y;
    const int m0 = blockIdx.x * MR;

    for (int i = tid; i < DIN * DOUT; i += 256)
        Ws[i] = W[(size_t)kb * DIN * DOUT + i];
    for (int i = tid; i < MR * DIN; i += 256) {
        int r = i >> 6, d = i & 63;
        int n = m0 + r;
        if (n > NN - 1) n = NN - 1;
        float v;
        if (!RED) {
            v = X[(size_t)n * DIN + d];
        } else {
            v = 0.f;
#pragma unroll
            for (int s = 0; s < SPLITS; s++) v += g_P1[((size_t)s * NN + n) * 64 + d];
            v = fmaxf(v, 0.f);
        }
        Xs[r * (DIN + 1) + d] = v;
    }
    __syncthreads();

    const int row = tid % MR;
    const int c0 = (tid / MR) * 8;
    float a[8];
#pragma unroll
    for (int c = 0; c < 8; c++) a[c] = 0.f;
#pragma unroll
    for (int d = 0; d < DIN; d++) {
        float xv = Xs[row * (DIN + 1) + d];
        float4 wa = *(const float4*)&Ws[d * DOUT + c0];
        float4 wb = *(const float4*)&Ws[d * DOUT + c0 + 4];
        a[0] = fmaf(xv, wa.x, a[0]); a[1] = fmaf(xv, wa.y, a[1]);
        a[2] = fmaf(xv, wa.z, a[2]); a[3] = fmaf(xv, wa.w, a[3]);
        a[4] = fmaf(xv, wb.x, a[4]); a[5] = fmaf(xv, wb.y, a[5]);
        a[6] = fmaf(xv, wb.z, a[6]); a[7] = fmaf(xv, wb.w, a[7]);
    }
    const int n = m0 + row;
    if (n < NN) {
#pragma unroll
        for (int c = 0; c < 8; c++) {
            float v = a[c];
            uint32_t u = __float_as_uint(v);
            uint32_t r = (u + 0x7FFFu + ((u >> 16) & 1u)) & 0xFFFF0000u;
            float lof = v - __uint_as_float(r);
            unsigned short ls;
            asm("cvt.rn.bf16.f32 %0, %1;" : "=h"(ls) : "f"(lof));
            size_t idx = ((size_t)(c0 + c) * KPOLY + kb) * NN + n;
            Th[idx] = (unsigned short)(r >> 16);
            Tl[idx] = ls;
        }
    }
}

// Final reduction of layer-1 partials into d_out
__global__ void reduce_out_kernel(float* __restrict__ out) {
    int i = blockIdx.x * blockDim.x + threadIdx.x;
    if (i < NN * 32 / 4) {
        float4 acc = make_float4(0.f, 0.f, 0.f, 0.f);
#pragma unroll
        for (int s = 0; s < SPLITS; s++) {
            float4 v = *(const float4*)(g_P2 + (size_t)s * NN * 32 + (size_t)i * 4);
            acc.x += v.x; acc.y += v.y; acc.z += v.z; acc.w += v.w;
        }
        *(float4*)(out + (size_t)i * 4) = acc;
    }
}

extern "C" void kernel_launch(void* const* d_in, const int* in_sizes, int n_in,
                              void* d_out, int out_size) {
    const float* x    = (const float*)d_in[0];
    const float* poly = (const float*)d_in[1];
    const float* W1   = (const float*)d_in[2];
    const float* W2   = (const float*)d_in[3];
    float* out = (float*)d_out;

    constexpr int SMEM64 = 3 * (2 * (MTILE * 32 * 2) + 2 * (64 * 40 * 2));  // 79872
    constexpr int SMEM32 = 3 * (2 * (MTILE * 32 * 2) + 2 * (32 * 40 * 2));  // 64512
    cudaFuncSetAttribute((const void*)poly_mma_kernel<64>,
                         cudaFuncAttributeMaxDynamicSharedMemorySize, SMEM64);
    cudaFuncSetAttribute((const void*)poly_mma_kernel<32>,
                         cudaFuncAttributeMaxDynamicSharedMemorySize, SMEM32);

    unsigned short *T1h, *T1l, *T2h, *T2l, *Ah, *Al;
    float *P1, *P2;
    cudaGetSymbolAddress((void**)&T1h, g_T1h);
    cudaGetSymbolAddress((void**)&T1l, g_T1l);
    cudaGetSymbolAddress((void**)&T2h, g_T2h);
    cudaGetSymbolAddress((void**)&T2l, g_T2l);
    cudaGetSymbolAddress((void**)&Ah, g_Ah);
    cudaGetSymbolAddress((void**)&Al, g_Al);
    cudaGetSymbolAddress((void**)&P1, g_P1);
    cudaGetSymbolAddress((void**)&P2, g_P2);

    dim3 g1((NN + 31) / 32, KPOLY);
    dim3 g2((NN + 63) / 64, KPOLY);
    dim3 gp(MT, SPLITS);
    const int psBlocks = (int)((TOTE / 16 + 255) / 256);  // 16 elems/thread

    presplit_kernel<<<psBlocks, 256>>>(poly, Ah, Al);            // poly -> hi/lo planes
    gemm_xw_kernel<64, false><<<g1, 256>>>(x, W1, T1h, T1l);     // T1^T hi/lo
    poly_mma_kernel<64><<<gp, 256, SMEM64>>>(T1h, T1l, Ah, Al, P1);
    gemm_xw_kernel<32, true><<<g2, 256>>>(x, W2, T2h, T2l);      // T2^T = relu(sum P1) @ W2
    poly_mma_kernel<32><<<gp, 256, SMEM32>>>(T2h, T2l, Ah, Al, P2);
    reduce_out_kernel<<<(NN * 32 / 4 + 255) / 256, 256>>>(out);
}